// round 7
// baseline (speedup 1.0000x reference)
#include <cuda_runtime.h>
#include <math.h>

// WaveNet (reference batch/time mixup: output [64,1,64]; only x[:,:,0:84] used).
//
// R7: 1 time point per lane. Each warp is fully independent (halo-redundant):
// warp (b, p) holds t in [2p-10, 2p+22) and, after 20 layers of edge erosion
// (right -1/layer always; left -1/layer for the 10 d=2 layers), lanes 10-11
// hold exactly the valid outputs t = 2p, 2p+1. 2048 warps = 64 batches x 32
// pairs, grid 512 x 128 (4 warps/block share SMEM weight staging).
// Gate weights pre-scaled by -log2(e) at staging so sigmoid = rcp(1+ex2(u)).

#define N_RES 20
#define FULL 0xFFFFFFFFu

__device__ __forceinline__ float ex2a(float x) {
    float y; asm("ex2.approx.ftz.f32 %0, %1;" : "=f"(y) : "f"(x)); return y;
}

__global__ void __launch_bounds__(128, 1)
wavenet_lane_kernel(const float* __restrict__ x,
                    const float* __restrict__ w_in,
                    const float* __restrict__ b_in,
                    const float* __restrict__ wd,
                    const float* __restrict__ bd,
                    const float* __restrict__ wg,
                    const float* __restrict__ bg,
                    const float* __restrict__ w_out,
                    const float* __restrict__ b_out,
                    float* __restrict__ out)
{
    __shared__ __align__(16) float swd[N_RES * 8];   // dilated conv weights
    __shared__ __align__(16) float swg[N_RES * 8];   // gate weights * (-log2 e)
    __shared__ __align__(16) float sbd[N_RES * 2];
    __shared__ __align__(16) float sbg[N_RES * 2];   // gate bias * (-log2 e)

    const int tid = threadIdx.x;
    const int l   = tid & 31;
    const int gw  = blockIdx.x * 4 + (tid >> 5);  // global warp id [0,2048)
    const int b   = gw >> 5;                      // batch
    const int p   = gw & 31;                      // output pair index
    const int t   = 2 * p - 10 + l;               // absolute time this lane owns

    const float NLOG2E = -1.4426950408889634f;
    for (int k = tid; k < N_RES * 8; k += 128) {
        swd[k] = wd[k];
        swg[k] = wg[k] * NLOG2E;
    }
    if (tid < N_RES * 2) { sbd[tid] = bd[tid]; sbg[tid] = bg[tid] * NLOG2E; }

    // conv_in (1x1, C=1 -> F=2); clamp t<0 reads (value irrelevant: garbage cone
    // never reaches lanes 10-11 — t=0's d=2 left tap is forced to pad 0)
    const float xv = x[(size_t)b * 32768 + (t > 0 ? t : 0)];
    float h0 = fmaf(w_in[0], xv, b_in[0]);
    float h1 = fmaf(w_in[1], xv, b_in[1]);
    float s0 = 0.0f, s1 = 0.0f;
    const bool pad0 = (t == 0);

    __syncthreads();   // weights staged

    const float4* wd4 = (const float4*)swd;
    const float4* wg4 = (const float4*)swg;
    const float2* bd2 = (const float2*)sbd;
    const float2* bg2 = (const float2*)sbg;

#pragma unroll
    for (int i = 0; i < N_RES; i++) {
        const bool d1 = (i < 10);

        // right taps h[t+1]
        float c0 = __shfl_down_sync(FULL, h0, 1);
        float c1 = __shfl_down_sync(FULL, h1, 1);
        // left taps: d=1 -> h[t]; d=2 -> h[t-1] (zero at absolute t=0)
        float a0, a1;
        if (d1) { a0 = h0; a1 = h1; }
        else {
            float u0 = __shfl_up_sync(FULL, h0, 1);
            float u1 = __shfl_up_sync(FULL, h1, 1);
            a0 = pad0 ? 0.0f : u0;
            a1 = pad0 ? 0.0f : u1;
        }

        const float4 wdv0 = wd4[2 * i], wdv1 = wd4[2 * i + 1];
        const float4 wgv0 = wg4[2 * i], wgv1 = wg4[2 * i + 1];
        const float2 bdv  = bd2[i];
        const float2 bgv  = bg2[i];

        float cd0 = fmaf(wdv0.x, a0, fmaf(wdv0.y, c0, bdv.x))
                  + fmaf(wdv0.z, a1, wdv0.w * c1);
        float cd1 = fmaf(wdv1.x, a0, fmaf(wdv1.y, c0, bdv.y))
                  + fmaf(wdv1.z, a1, wdv1.w * c1);
        float ug0 = fmaf(wgv0.x, a0, fmaf(wgv0.y, c0, bgv.x))
                  + fmaf(wgv0.z, a1, wgv0.w * c1);   // = -cg*log2e
        float ug1 = fmaf(wgv1.x, a0, fmaf(wgv1.y, c0, bgv.y))
                  + fmaf(wgv1.z, a1, wgv1.w * c1);

        float g0 = __fdividef(cd0, 1.0f + ex2a(ug0));
        float g1 = __fdividef(cd1, 1.0f + ex2a(ug1));

        s0 += g0;
        s1 += g1;
        h0 = (d1 ? c0 : h0) + g0;
        h1 = (d1 ? c1 : h1) + g1;
    }

    // conv_out over relu(skip sum); valid lanes are exactly 10 and 11
    if (l == 10 || l == 11) {
        out[(size_t)b * 64 + t] =
            fmaf(w_out[0], fmaxf(s0, 0.0f),
            fmaf(w_out[1], fmaxf(s1, 0.0f), b_out[0]));
    }
}

extern "C" void kernel_launch(void* const* d_in, const int* in_sizes, int n_in,
                              void* d_out, int out_size)
{
    const float* x     = (const float*)d_in[0];
    const float* w_in  = (const float*)d_in[1];
    const float* b_in  = (const float*)d_in[2];
    const float* wd    = (const float*)d_in[3];
    const float* bd    = (const float*)d_in[4];
    const float* wg    = (const float*)d_in[5];
    const float* bg    = (const float*)d_in[6];
    const float* w_out = (const float*)d_in[7];
    const float* b_out = (const float*)d_in[8];
    float* out = (float*)d_out;

    wavenet_lane_kernel<<<512, 128>>>(x, w_in, b_in, wd, bd, wg, bg,
                                      w_out, b_out, out);
}

// round 8
// speedup vs baseline: 1.3478x; 1.3478x over previous
#include <cuda_runtime.h>
#include <math.h>

// WaveNet (reference batch/time mixup: output [64,1,64]; only x[:,:,0:84] used).
//
// R8 = R6 (2 halo-redundant warps/batch, 2 pts/lane, barrier-free loop)
//    + HW tanh sigmoid: sigmoid(cg) = 0.5*(1+tanh(cg/2)).
//      0.5 folded into staged gate weights (tanh arg) and into staged dilated
//      weights (cdh = cd/2), so per value: 1 MUFU.TANH + 1 FMA instead of
//      EX2 + ADD + RCP + MUL (-20 cyc/layer on the serial chain, MUFU 8->4).

#define N_RES 20
#define FULL 0xFFFFFFFFu

__device__ __forceinline__ float tanha(float x) {
    float y; asm("tanh.approx.f32 %0, %1;" : "=f"(y) : "f"(x)); return y;
}

__global__ void __launch_bounds__(64, 1)
wavenet_halo_kernel(const float* __restrict__ x,
                    const float* __restrict__ w_in,
                    const float* __restrict__ b_in,
                    const float* __restrict__ wd,
                    const float* __restrict__ bd,
                    const float* __restrict__ wg,
                    const float* __restrict__ bg,
                    const float* __restrict__ w_out,
                    const float* __restrict__ b_out,
                    float* __restrict__ out)
{
    __shared__ __align__(16) float swd[N_RES * 8];   // 0.5 * dilated weights
    __shared__ __align__(16) float swg[N_RES * 8];   // 0.5 * gate weights
    __shared__ __align__(16) float sbd[N_RES * 2];   // 0.5 * dilated bias
    __shared__ __align__(16) float sbg[N_RES * 2];   // 0.5 * gate bias

    const int b   = blockIdx.x;
    const int tid = threadIdx.x;
    const int w   = tid >> 5;         // warp 0 / 1
    const int l   = tid & 31;

    // ---- stage half-scaled weights + biases to SMEM ----
    for (int k = tid; k < N_RES * 8; k += 64) {
        swd[k] = 0.5f * wd[k];
        swg[k] = 0.5f * wg[k];
    }
    if (tid < N_RES * 2) { sbd[tid] = 0.5f * bd[tid]; sbg[tid] = 0.5f * bg[tid]; }

    const int base = w * 20;          // warp0 holds [0,64), warp1 holds [20,84)
    const int t0   = base + 2 * l;    // slot0 absolute time; slot1 = t0+1

    // output ownership (warp0 -> [0,32), warp1 -> [32,64))
    const bool o0 = w ? (t0     >= 32 && t0     < 64) : (t0     < 32);
    const bool o1 = w ? (t0 + 1 >= 32 && t0 + 1 < 64) : (t0 + 1 < 32);
    const bool pad0 = (w == 0 && l == 0);   // absolute t==0: d=2 left tap is pad

    // ---- conv_in: 1x1, C=1 -> F=2 ----
    const float wi0 = w_in[0], wi1 = w_in[1];
    const float bi0 = b_in[0], bi1 = b_in[1];
    const float xv0 = x[(size_t)b * 32768 + t0];
    const float xv1 = x[(size_t)b * 32768 + t0 + 1];
    float h0[2], h1[2];
    h0[0] = fmaf(wi0, xv0, bi0);  h0[1] = fmaf(wi0, xv1, bi0);
    h1[0] = fmaf(wi1, xv0, bi1);  h1[1] = fmaf(wi1, xv1, bi1);

    float s0[2] = {0.0f, 0.0f};
    float s1[2] = {0.0f, 0.0f};

    __syncthreads();                  // weights staged (once)

    const float4* wd4 = (const float4*)swd;
    const float4* wg4 = (const float4*)swg;
    const float2* bd2 = (const float2*)sbd;
    const float2* bg2 = (const float2*)sbg;

#pragma unroll
    for (int i = 0; i < N_RES; i++) {
        const bool d1 = (i < 10);

        // right taps c = h[t+1]
        float c0s0 = h0[1], c1s0 = h1[1];
        float c0s1 = __shfl_down_sync(FULL, h0[0], 1);
        float c1s1 = __shfl_down_sync(FULL, h1[0], 1);

        // left taps: d=1 -> h[t]; d=2 -> h[t-1] (zero at absolute t=0)
        float a0s0, a1s0, a0s1, a1s1;
        if (d1) {
            a0s0 = h0[0]; a1s0 = h1[0];
            a0s1 = h0[1]; a1s1 = h1[1];
        } else {
            float u0 = __shfl_up_sync(FULL, h0[1], 1);
            float u1 = __shfl_up_sync(FULL, h1[1], 1);
            a0s0 = pad0 ? 0.0f : u0;
            a1s0 = pad0 ? 0.0f : u1;
            a0s1 = h0[0];
            a1s1 = h1[0];
        }

        const float4 wdv0 = wd4[2 * i], wdv1 = wd4[2 * i + 1];
        const float4 wgv0 = wg4[2 * i], wgv1 = wg4[2 * i + 1];
        const float2 bdv  = bd2[i];
        const float2 bgv  = bg2[i];

        // ---- slot 0 ----
        {
            float cdh0 = fmaf(wdv0.x, a0s0, fmaf(wdv0.y, c0s0, bdv.x))
                       + fmaf(wdv0.z, a1s0, wdv0.w * c1s0);     // = cd0/2
            float cdh1 = fmaf(wdv1.x, a0s0, fmaf(wdv1.y, c0s0, bdv.y))
                       + fmaf(wdv1.z, a1s0, wdv1.w * c1s0);
            float u0g  = fmaf(wgv0.x, a0s0, fmaf(wgv0.y, c0s0, bgv.x))
                       + fmaf(wgv0.z, a1s0, wgv0.w * c1s0);     // = cg0/2
            float u1g  = fmaf(wgv1.x, a0s0, fmaf(wgv1.y, c0s0, bgv.y))
                       + fmaf(wgv1.z, a1s0, wgv1.w * c1s0);
            float g0 = fmaf(cdh0, tanha(u0g), cdh0);            // cd*sigmoid(cg)
            float g1 = fmaf(cdh1, tanha(u1g), cdh1);
            if (o0) { s0[0] += g0; s1[0] += g1; }
            h0[0] = (d1 ? c0s0 : h0[0]) + g0;
            h1[0] = (d1 ? c1s0 : h1[0]) + g1;
        }
        // ---- slot 1 ----
        {
            float cdh0 = fmaf(wdv0.x, a0s1, fmaf(wdv0.y, c0s1, bdv.x))
                       + fmaf(wdv0.z, a1s1, wdv0.w * c1s1);
            float cdh1 = fmaf(wdv1.x, a0s1, fmaf(wdv1.y, c0s1, bdv.y))
                       + fmaf(wdv1.z, a1s1, wdv1.w * c1s1);
            float u0g  = fmaf(wgv0.x, a0s1, fmaf(wgv0.y, c0s1, bgv.x))
                       + fmaf(wgv0.z, a1s1, wgv0.w * c1s1);
            float u1g  = fmaf(wgv1.x, a0s1, fmaf(wgv1.y, c0s1, bgv.y))
                       + fmaf(wgv1.z, a1s1, wgv1.w * c1s1);
            float g0 = fmaf(cdh0, tanha(u0g), cdh0);
            float g1 = fmaf(cdh1, tanha(u1g), cdh1);
            if (o1) { s0[1] += g0; s1[1] += g1; }
            h0[1] = (d1 ? c0s1 : h0[1]) + g0;
            h1[1] = (d1 ? c1s1 : h1[1]) + g1;
        }
    }

    // ---- conv_out over relu(per-point skip sum) ----
    const float wo0 = w_out[0], wo1 = w_out[1], bo = b_out[0];
    if (o0) {
        out[(size_t)b * 64 + t0] =
            fmaf(wo0, fmaxf(s0[0], 0.0f), fmaf(wo1, fmaxf(s1[0], 0.0f), bo));
    }
    if (o1) {
        out[(size_t)b * 64 + t0 + 1] =
            fmaf(wo0, fmaxf(s0[1], 0.0f), fmaf(wo1, fmaxf(s1[1], 0.0f), bo));
    }
}

extern "C" void kernel_launch(void* const* d_in, const int* in_sizes, int n_in,
                              void* d_out, int out_size)
{
    const float* x     = (const float*)d_in[0];
    const float* w_in  = (const float*)d_in[1];
    const float* b_in  = (const float*)d_in[2];
    const float* wd    = (const float*)d_in[3];
    const float* bd    = (const float*)d_in[4];
    const float* wg    = (const float*)d_in[5];
    const float* bg    = (const float*)d_in[6];
    const float* w_out = (const float*)d_in[7];
    const float* b_out = (const float*)d_in[8];
    float* out = (float*)d_out;

    wavenet_halo_kernel<<<64, 64>>>(x, w_in, b_in, wd, bd, wg, bg,
                                    w_out, b_out, out);
}